// round 11
// baseline (speedup 1.0000x reference)
#include <cuda_runtime.h>
#include <cuda_bf16.h>
#include <cstdint>

#define NQ 32768          // B*H*W queries
#define KC 1024           // codebook entries
#define DD 256            // embedding dim
#define ZQ_ELEMS 8388608  // 32*256*32*32
#define CAP 16
#define EPS 2.5e-4f

// ---------------------------------------------------------------------------
// Device-global scratch (allocation-free rule)
// ---------------------------------------------------------------------------
__device__ float g_cnorm[KC];
__device__ float g_znorm[NQ];
__device__ int   g_idx[NQ];
__device__ float g_part[256];
__device__ int   g_cnt[NQ];
__device__ int   g_cand[NQ * CAP];
__device__ float g_zt[(size_t)NQ * DD];
__device__ __nv_bfloat16 g_cbh[KC * DD];
__device__ __nv_bfloat16 g_cbl[KC * DD];
__device__ __nv_bfloat16 g_zh[(size_t)NQ * DD];
__device__ __nv_bfloat16 g_zl[(size_t)NQ * DD];

// ---------------------------------------------------------------------------
// PTX helpers (baseline ISA only: cp.async, ldmatrix, mma.sync — sm_80+)
// ---------------------------------------------------------------------------
__device__ __forceinline__ uint32_t smem_u32(const void* p) {
    uint32_t a;
    asm("{ .reg .u64 t; cvta.to.shared.u64 t, %1; cvt.u32.u64 %0, t; }"
        : "=r"(a) : "l"(p));
    return a;
}
__device__ __forceinline__ void cp_async16(uint32_t saddr, const void* g) {
    asm volatile("cp.async.cg.shared.global [%0], [%1], 16;"
                 :: "r"(saddr), "l"(g) : "memory");
}
#define CP_COMMIT() asm volatile("cp.async.commit_group;" ::: "memory")
#define CP_WAIT1()  asm volatile("cp.async.wait_group 1;" ::: "memory")
#define CP_WAIT0()  asm volatile("cp.async.wait_group 0;" ::: "memory")

__device__ __forceinline__ void ldsm4(uint32_t* r, uint32_t addr) {
    asm volatile("ldmatrix.sync.aligned.m8n8.x4.shared.b16 {%0,%1,%2,%3}, [%4];"
                 : "=r"(r[0]), "=r"(r[1]), "=r"(r[2]), "=r"(r[3]) : "r"(addr));
}
__device__ __forceinline__ void mma_bf16(float* d, const uint32_t* a,
                                         const uint32_t* b) {
    asm volatile(
        "mma.sync.aligned.m16n8k16.row.col.f32.bf16.bf16.f32 "
        "{%0,%1,%2,%3}, {%4,%5,%6,%7}, {%8,%9}, {%0,%1,%2,%3};"
        : "+f"(d[0]), "+f"(d[1]), "+f"(d[2]), "+f"(d[3])
        : "r"(a[0]), "r"(a[1]), "r"(a[2]), "r"(a[3]), "r"(b[0]), "r"(b[1]));
}

// ---------------------------------------------------------------------------
// Prep kernels
// ---------------------------------------------------------------------------
__global__ void cnorm_kernel(const float* __restrict__ cb) {
    int k = blockIdx.x * blockDim.x + threadIdx.x;
    if (k < KC) {
        const float* row = cb + (size_t)k * DD;
        float s = 0.f;
        for (int d = 0; d < DD; ++d) {
            float v = row[d];
            s = __fadd_rn(s, __fmul_rn(v, v));
        }
        g_cnorm[k] = s;
    }
}

__global__ void prep_cb_kernel(const float* __restrict__ cb) {
    int i = blockIdx.x * 256 + threadIdx.x;
    float v = cb[i];
    __nv_bfloat16 h = __float2bfloat16(v);
    g_cbh[i] = h;
    g_cbl[i] = __float2bfloat16(v - __bfloat162float(h));
}

// NCHW -> [query, d] fp32 + bf16 hi/lo transpose
__global__ void prep_z_kernel(const float* __restrict__ z) {
    __shared__ float tile[32][33];
    const int hw0 = blockIdx.x * 32;
    const int b   = blockIdx.y;
    const int c0  = blockIdx.z * 32;
    const int tx = threadIdx.x, ty = threadIdx.y;

    #pragma unroll
    for (int i = 0; i < 4; ++i) {
        int c = c0 + ty + i * 8;
        tile[ty + i * 8][tx] = z[((size_t)(b * 256 + c)) * 1024 + hw0 + tx];
    }
    __syncthreads();
    #pragma unroll
    for (int i = 0; i < 4; ++i) {
        int q = ty + i * 8;
        size_t n = (size_t)b * 1024 + hw0 + q;
        float v = tile[tx][q];
        __nv_bfloat16 h = __float2bfloat16(v);
        g_zt[n * 256 + c0 + tx] = v;
        g_zh[n * 256 + c0 + tx] = h;
        g_zl[n * 256 + c0 + tx] = __float2bfloat16(v - __bfloat162float(h));
    }
}

// query norms (identical summation shape to round-2 passing kernel) + cnt zero
__global__ __launch_bounds__(256) void znorm_kernel(const float* __restrict__ z) {
    __shared__ float red[256];
    const int t  = threadIdx.x;
    const int n0 = blockIdx.x * 128;
    const int b  = n0 >> 10;
    const int hw0 = n0 & 1023;
    const int q = t & 127, half = t >> 7;
    const float* base = z + ((size_t)(b * 256 + half * 128)) * 1024 + hw0 + q;
    float s = 0.f;
    #pragma unroll 4
    for (int d = 0; d < 128; ++d) {
        float v = base[(size_t)d * 1024];
        s = __fadd_rn(s, __fmul_rn(v, v));
    }
    red[t] = s;
    __syncthreads();
    if (t < 128) {
        g_znorm[n0 + t] = __fadd_rn(red[t], red[t + 128]);
        g_cnt[n0 + t] = 0;
    }
}

// ---------------------------------------------------------------------------
// Split-bf16 HMMA distance GEMM + approx argmin + near-tie candidate collection
// ---------------------------------------------------------------------------
#define A_ROWB   1040
#define A_BYTES  (128 * A_ROWB)       // 133120
#define B_ROWB   144
#define B_STAGE  (128 * B_ROWB)       // 18432
#define DYN_SMEM (A_BYTES + 2 * B_STAGE)

__global__ __launch_bounds__(256, 1) void hmma_argmin_kernel() {
    extern __shared__ __align__(16) char dsm[];
    __shared__ float cn_s[KC];
    __shared__ float zn_s[128];

    const int t    = threadIdx.x;
    const int lane = t & 31;
    const int warp = t >> 5;
    const int warp_m = warp >> 1;     // 0..3  (32 rows each)
    const int warp_n = warp & 1;      // 0..1  (64 cols each)
    const int q0   = blockIdx.x * 128;

    const uint32_t a_base = smem_u32(dsm);
    const uint32_t b_base = a_base + A_BYTES;

    for (int i = t; i < KC; i += 256) cn_s[i] = g_cnorm[i];
    if (t < 128) zn_s[t] = g_znorm[q0 + t];

    // ---- prologue: A (all 8192 x 16B) + B chunk 0, one cp.async group ----
    #pragma unroll 8
    for (int i = 0; i < 32; ++i) {
        int o = t + 256 * i;
        int row = o >> 6, u = o & 63;
        const __nv_bfloat16* src = (u < 32)
            ? g_zh + (size_t)(q0 + row) * 256 + u * 8
            : g_zl + (size_t)(q0 + row) * 256 + (u - 32) * 8;
        cp_async16(a_base + row * A_ROWB + u * 16, src);
    }
    #pragma unroll
    for (int i = 0; i < 4; ++i) {
        int o = t + 256 * i;
        int row = o >> 3, u = o & 7;
        cp_async16(b_base + row * B_ROWB + u * 16,
                   g_cbh + (size_t)row * 256 + u * 8);
    }
    CP_COMMIT();

    float acc[2][8][4];
    #pragma unroll
    for (int m = 0; m < 2; ++m)
        #pragma unroll
        for (int j = 0; j < 8; ++j)
            #pragma unroll
            for (int r = 0; r < 4; ++r) acc[m][j][r] = 0.f;

    float bestv[4] = {3.4e38f, 3.4e38f, 3.4e38f, 3.4e38f};
    int   besti[4] = {0, 0, 0, 0};

    // ldmatrix lane addressing (conflict-free: row strides are odd 16B units)
    const int a_ro = (lane & 7) + ((lane >> 3) & 1) * 8;
    const int a_lc = lane >> 4;
    const int b_ro = (lane & 7) + ((lane >> 4) & 1) * 8;
    const int b_lc = (lane >> 3) & 1;
    const uint32_t a_ptr0 = a_base + (warp_m * 32 + a_ro) * A_ROWB + a_lc * 16;
    const uint32_t b_ptr0 = b_base + (warp_n * 64 + b_ro) * B_ROWB + b_lc * 16;

    // 96 chunks: ntile = gc/12, c = gc%12; pass p=c/4 (0:zh*ch 1:zh*cl 2:zl*ch)
    for (int gc = 0; gc < 96; ++gc) {
        const int s  = gc & 1;
        const int nt = gc / 12;
        const int c  = gc % 12;

        if (gc + 1 < 96) {
            const int gn  = gc + 1;
            const int nt2 = gn / 12, c2 = gn % 12;
            const int p2 = c2 >> 2, kc2 = c2 & 3;
            const __nv_bfloat16* bsrc = (p2 == 1) ? g_cbl : g_cbh;
            const uint32_t dst = b_base + (uint32_t)(s ^ 1) * B_STAGE;
            #pragma unroll
            for (int i = 0; i < 4; ++i) {
                int o = t + 256 * i;
                int row = o >> 3, u = o & 7;
                cp_async16(dst + row * B_ROWB + u * 16,
                           bsrc + (size_t)(nt2 * 128 + row) * 256 + kc2 * 64 + u * 8);
            }
            CP_COMMIT();
            CP_WAIT1();
        } else {
            CP_WAIT0();
        }
        __syncthreads();

        const int p  = c >> 2, kc = c & 3;
        const uint32_t ap = a_ptr0 + (uint32_t)(((p == 2) ? 32 : 0) + kc * 8) * 16;
        const uint32_t bp = b_ptr0 + (uint32_t)s * B_STAGE;

        #pragma unroll
        for (int j = 0; j < 4; ++j) {
            uint32_t a0[4], a1[4];
            ldsm4(a0, ap + j * 32);
            ldsm4(a1, ap + 16 * A_ROWB + j * 32);
            #pragma unroll
            for (int q = 0; q < 4; ++q) {
                uint32_t bq[4];
                ldsm4(bq, bp + q * (16 * B_ROWB) + j * 32);
                mma_bf16(acc[0][2 * q + 0], a0, bq + 0);
                mma_bf16(acc[0][2 * q + 1], a0, bq + 2);
                mma_bf16(acc[1][2 * q + 0], a1, bq + 0);
                mma_bf16(acc[1][2 * q + 1], a1, bq + 2);
            }
        }

        // end-of-code-tile epilogue: scores, running best, candidate collection
        if (c == 11) {
            #pragma unroll
            for (int m = 0; m < 2; ++m) {
                #pragma unroll
                for (int rh = 0; rh < 2; ++rh) {
                    const int sl = m * 2 + rh;
                    const float zn = zn_s[warp_m * 32 + m * 16 + rh * 8 + (lane >> 2)];
                    float sc16[16];
                    #pragma unroll
                    for (int jn = 0; jn < 8; ++jn) {
                        const int k0 = nt * 128 + warp_n * 64 + jn * 8 + (lane & 3) * 2;
                        float a0 = acc[m][jn][rh * 2 + 0];
                        float a1 = acc[m][jn][rh * 2 + 1];
                        sc16[2 * jn]     = __fadd_rn(__fadd_rn(zn, cn_s[k0]),
                                                     __fmul_rn(-2.f, a0));
                        sc16[2 * jn + 1] = __fadd_rn(__fadd_rn(zn, cn_s[k0 + 1]),
                                                     __fmul_rn(-2.f, a1));
                        acc[m][jn][rh * 2 + 0] = 0.f;
                        acc[m][jn][rh * 2 + 1] = 0.f;
                    }
                    #pragma unroll
                    for (int i = 0; i < 16; ++i) {
                        int k = nt * 128 + warp_n * 64 + (i >> 1) * 8
                              + (lane & 3) * 2 + (i & 1);
                        if (sc16[i] < bestv[sl]) { bestv[sl] = sc16[i]; besti[sl] = k; }
                    }
                    // warp-quad running min -> collection threshold
                    float qm = bestv[sl];
                    qm = fminf(qm, __shfl_xor_sync(0xffffffffu, qm, 1));
                    qm = fminf(qm, __shfl_xor_sync(0xffffffffu, qm, 2));
                    const float thr = qm + EPS;
                    const int rowg = q0 + warp_m * 32 + m * 16 + rh * 8 + (lane >> 2);
                    #pragma unroll
                    for (int i = 0; i < 16; ++i) {
                        if (sc16[i] < thr) {
                            int k = nt * 128 + warp_n * 64 + (i >> 1) * 8
                                  + (lane & 3) * 2 + (i & 1);
                            int pos = atomicAdd(&g_cnt[rowg], 1);
                            if (pos < CAP) g_cand[rowg * CAP + pos] = k;
                        }
                    }
                }
            }
        }
        __syncthreads();   // all warps done with stage s before it is refilled
    }
}

// ---------------------------------------------------------------------------
// Exact fp32 re-rank of collected candidates (round-2 arithmetic, bit-matched)
// one warp per query; lex-min (value, index) = jnp.argmin semantics.
// ---------------------------------------------------------------------------
__global__ __launch_bounds__(256) void rerank_kernel(const float* __restrict__ cb) {
    const int warp = threadIdx.x >> 5, lane = threadIdx.x & 31;
    const int q = blockIdx.x * 8 + warp;   // FIX: 8 warps per block, NQ/8 blocks
    const int cnt = g_cnt[q];

    if (cnt == 1) {                       // unique candidate: already the winner
        if (lane == 0) g_idx[q] = g_cand[q * CAP];
        return;
    }

    const float zn = g_znorm[q];
    const float* zr = g_zt + (size_t)q * DD;
    float bv = 3.4e38f;
    int   bi = 0x7FFFFFFF;

    if (cnt <= CAP) {
        if (lane < cnt) {
            int k = g_cand[q * CAP + lane];
            const float* cr = cb + (size_t)k * DD;
            float acc = 0.f;
            for (int d = 0; d < DD; ++d) acc = fmaf(zr[d], cr[d], acc);
            bv = __fadd_rn(__fadd_rn(zn, g_cnorm[k]), __fmul_rn(-2.f, acc));
            bi = k;
        }
    } else {                              // overflow fallback: full exact scan
        for (int k = lane; k < KC; k += 32) {
            const float* cr = cb + (size_t)k * DD;
            float acc = 0.f;
            for (int d = 0; d < DD; ++d) acc = fmaf(zr[d], cr[d], acc);
            float sc = __fadd_rn(__fadd_rn(zn, g_cnorm[k]), __fmul_rn(-2.f, acc));
            if (sc < bv || (sc == bv && k < bi)) { bv = sc; bi = k; }
        }
    }
    #pragma unroll
    for (int off = 16; off >= 1; off >>= 1) {
        float v2 = __shfl_xor_sync(0xffffffffu, bv, off);
        int   i2 = __shfl_xor_sync(0xffffffffu, bi, off);
        if (v2 < bv || (v2 == bv && i2 < bi)) { bv = v2; bi = i2; }
    }
    if (lane == 0) g_idx[q] = bi;
}

// ---------------------------------------------------------------------------
// Gather z_q (NCHW via smem transpose) + loss partials
// ---------------------------------------------------------------------------
__global__ __launch_bounds__(256) void gather_kernel(
        const float* __restrict__ z, const float* __restrict__ cb,
        float* __restrict__ out_zq, float* __restrict__ out_idxf) {
    __shared__ float tile[32][129];
    __shared__ int   idx_s[128];
    __shared__ float red[256];

    const int t   = threadIdx.x;
    const int n0  = blockIdx.x * 128;
    const int b   = n0 >> 10;
    const int hw0 = n0 & 1023;

    if (t < 128) {
        int id = g_idx[n0 + t];
        idx_s[t] = id;
        out_idxf[n0 + t] = (float)id;
    }
    __syncthreads();

    float lsum = 0.f;
    for (int c0 = 0; c0 < DD; c0 += 32) {
        {
            int q = t >> 1, part = t & 1;
            const float* src = cb + (size_t)idx_s[q] * DD + c0 + part * 16;
            #pragma unroll
            for (int u = 0; u < 4; ++u) {
                float4 v = *reinterpret_cast<const float4*>(src + u * 4);
                int cc = part * 16 + u * 4;
                tile[cc + 0][q] = v.x; tile[cc + 1][q] = v.y;
                tile[cc + 2][q] = v.z; tile[cc + 3][q] = v.w;
            }
        }
        __syncthreads();
        #pragma unroll
        for (int i = 0; i < 16; ++i) {
            int lin = t + 256 * i;
            int cc  = lin >> 7;
            int q   = lin & 127;
            size_t gaddr = ((size_t)(b * 256 + c0 + cc)) * 1024 + hw0 + q;
            float v  = tile[cc][q];
            out_zq[gaddr] = v;
            float dv = v - z[gaddr];
            lsum = fmaf(dv, dv, lsum);
        }
        __syncthreads();
    }

    red[t] = lsum;
    __syncthreads();
    for (int s = 128; s > 0; s >>= 1) {
        if (t < s) red[t] += red[t + s];
        __syncthreads();
    }
    if (t == 0) g_part[blockIdx.x] = red[0];
}

__global__ void loss_kernel(float* __restrict__ out_loss) {
    __shared__ float red[256];
    int t = threadIdx.x;
    red[t] = g_part[t];
    __syncthreads();
    for (int s = 128; s > 0; s >>= 1) {
        if (t < s) red[t] += red[t + s];
        __syncthreads();
    }
    if (t == 0) out_loss[0] = 1.25f * red[0] / (float)ZQ_ELEMS;
}

// ---------------------------------------------------------------------------
extern "C" void kernel_launch(void* const* d_in, const int* in_sizes, int n_in,
                              void* d_out, int out_size) {
    const float* z  = (const float*)d_in[0];   // [32,256,32,32]
    const float* cb = (const float*)d_in[1];   // [1024,256]
    float* out      = (float*)d_out;
    float* out_zq   = out;
    float* out_loss = out + ZQ_ELEMS;
    float* out_idxf = out + ZQ_ELEMS + 1;

    cudaFuncSetAttribute(hmma_argmin_kernel,
                         cudaFuncAttributeMaxDynamicSharedMemorySize, DYN_SMEM);

    cnorm_kernel<<<4, 256>>>(cb);
    prep_cb_kernel<<<KC * DD / 256, 256>>>(cb);
    prep_z_kernel<<<dim3(32, 32, 8), dim3(32, 8)>>>(z);
    znorm_kernel<<<NQ / 128, 256>>>(z);
    hmma_argmin_kernel<<<NQ / 128, 256, DYN_SMEM>>>();
    rerank_kernel<<<NQ / 8, 256>>>(cb);        // FIX: one warp per query
    gather_kernel<<<NQ / 128, 256>>>(z, cb, out_zq, out_idxf);
    loss_kernel<<<1, 256>>>(out_loss);
}

// round 13
// speedup vs baseline: 1.4166x; 1.4166x over previous
#include <cuda_runtime.h>
#include <cuda_bf16.h>
#include <cstdint>

#define NQ 32768          // B*H*W queries
#define KC 1024           // codebook entries
#define DD 256            // embedding dim
#define ZQ_ELEMS 8388608  // 32*256*32*32
#define CAP 32
#define EPS 1.0e-3f

// ---------------------------------------------------------------------------
// Device-global scratch (allocation-free rule)
// ---------------------------------------------------------------------------
__device__ float g_cnorm[KC];
__device__ float g_znorm[NQ];
__device__ int   g_idx[NQ];
__device__ float g_part[256];
__device__ int   g_cnt[NQ];
__device__ int   g_cand[NQ * CAP];
__device__ float g_zt[(size_t)NQ * DD];
__device__ __nv_bfloat16 g_cbh[KC * DD];
__device__ __nv_bfloat16 g_zh[(size_t)NQ * DD];

// ---------------------------------------------------------------------------
// PTX helpers (baseline ISA only: cp.async, ldmatrix, mma.sync — sm_80+)
// ---------------------------------------------------------------------------
__device__ __forceinline__ uint32_t smem_u32(const void* p) {
    uint32_t a;
    asm("{ .reg .u64 t; cvta.to.shared.u64 t, %1; cvt.u32.u64 %0, t; }"
        : "=r"(a) : "l"(p));
    return a;
}
__device__ __forceinline__ void cp_async16(uint32_t saddr, const void* g) {
    asm volatile("cp.async.cg.shared.global [%0], [%1], 16;"
                 :: "r"(saddr), "l"(g) : "memory");
}
#define CP_COMMIT() asm volatile("cp.async.commit_group;" ::: "memory")
#define CP_WAIT1()  asm volatile("cp.async.wait_group 1;" ::: "memory")
#define CP_WAIT0()  asm volatile("cp.async.wait_group 0;" ::: "memory")

__device__ __forceinline__ void ldsm4(uint32_t* r, uint32_t addr) {
    asm volatile("ldmatrix.sync.aligned.m8n8.x4.shared.b16 {%0,%1,%2,%3}, [%4];"
                 : "=r"(r[0]), "=r"(r[1]), "=r"(r[2]), "=r"(r[3]) : "r"(addr));
}
__device__ __forceinline__ void mma_bf16(float* d, const uint32_t* a,
                                         const uint32_t* b) {
    asm volatile(
        "mma.sync.aligned.m16n8k16.row.col.f32.bf16.bf16.f32 "
        "{%0,%1,%2,%3}, {%4,%5,%6,%7}, {%8,%9}, {%0,%1,%2,%3};"
        : "+f"(d[0]), "+f"(d[1]), "+f"(d[2]), "+f"(d[3])
        : "r"(a[0]), "r"(a[1]), "r"(a[2]), "r"(a[3]), "r"(b[0]), "r"(b[1]));
}

// ---------------------------------------------------------------------------
// Prep kernels
// ---------------------------------------------------------------------------
__global__ void cnorm_kernel(const float* __restrict__ cb) {
    int k = blockIdx.x * blockDim.x + threadIdx.x;
    if (k < KC) {
        const float* row = cb + (size_t)k * DD;
        float s = 0.f;
        for (int d = 0; d < DD; ++d) {
            float v = row[d];
            s = __fadd_rn(s, __fmul_rn(v, v));
        }
        g_cnorm[k] = s;
    }
}

__global__ void prep_cb_kernel(const float* __restrict__ cb) {
    int i = blockIdx.x * 256 + threadIdx.x;
    g_cbh[i] = __float2bfloat16(cb[i]);
}

// NCHW -> [query, d] fp32 + bf16 transpose
__global__ void prep_z_kernel(const float* __restrict__ z) {
    __shared__ float tile[32][33];
    const int hw0 = blockIdx.x * 32;
    const int b   = blockIdx.y;
    const int c0  = blockIdx.z * 32;
    const int tx = threadIdx.x, ty = threadIdx.y;

    #pragma unroll
    for (int i = 0; i < 4; ++i) {
        int c = c0 + ty + i * 8;
        tile[ty + i * 8][tx] = z[((size_t)(b * 256 + c)) * 1024 + hw0 + tx];
    }
    __syncthreads();
    #pragma unroll
    for (int i = 0; i < 4; ++i) {
        int q = ty + i * 8;
        size_t n = (size_t)b * 1024 + hw0 + q;
        float v = tile[tx][q];
        g_zt[n * 256 + c0 + tx] = v;
        g_zh[n * 256 + c0 + tx] = __float2bfloat16(v);
    }
}

// query norms (identical summation shape to round-2 passing kernel) + cnt zero
__global__ __launch_bounds__(256) void znorm_kernel(const float* __restrict__ z) {
    __shared__ float red[256];
    const int t  = threadIdx.x;
    const int n0 = blockIdx.x * 128;
    const int b  = n0 >> 10;
    const int hw0 = n0 & 1023;
    const int q = t & 127, half = t >> 7;
    const float* base = z + ((size_t)(b * 256 + half * 128)) * 1024 + hw0 + q;
    float s = 0.f;
    #pragma unroll 4
    for (int d = 0; d < 128; ++d) {
        float v = base[(size_t)d * 1024];
        s = __fadd_rn(s, __fmul_rn(v, v));
    }
    red[t] = s;
    __syncthreads();
    if (t < 128) {
        g_znorm[n0 + t] = __fadd_rn(red[t], red[t + 128]);
        g_cnt[n0 + t] = 0;
    }
}

// ---------------------------------------------------------------------------
// SINGLE-PASS bf16 HMMA distance GEMM + candidate collection.
// The exact fp32 rerank decides the final index, so the GEMM only needs to be
// accurate to << EPS; single bf16 error (6 sigma) ~ 4e-4 < EPS/2 = 5e-4.
// CTA = 128 queries x 1024 codes, K = 256 (zh*ch only).
// A resident: 128 rows x 256 bf16, row pad 528B (odd 16B stride).
// B streamed: 128-code x 64-K chunks, pad 144B, double-buffered. 32 chunks.
// smem ~102KB -> 2 CTAs/SM.
// ---------------------------------------------------------------------------
#define A_ROWB   528
#define A_BYTES  (128 * A_ROWB)       // 67584
#define B_ROWB   144
#define B_STAGE  (128 * B_ROWB)       // 18432
#define DYN_SMEM (A_BYTES + 2 * B_STAGE)   // 104448

__global__ __launch_bounds__(256, 2) void hmma_argmin_kernel() {
    extern __shared__ __align__(16) char dsm[];
    __shared__ float cn_s[KC];
    __shared__ float zn_s[128];

    const int t    = threadIdx.x;
    const int lane = t & 31;
    const int warp = t >> 5;
    const int warp_m = warp >> 1;     // 0..3  (32 rows each)
    const int warp_n = warp & 1;      // 0..1  (64 cols each)
    const int q0   = blockIdx.x * 128;

    const uint32_t a_base = smem_u32(dsm);
    const uint32_t b_base = a_base + A_BYTES;

    for (int i = t; i < KC; i += 256) cn_s[i] = g_cnorm[i];
    if (t < 128) zn_s[t] = g_znorm[q0 + t];

    // ---- prologue: A (4096 x 16B) + B chunk 0, one cp.async group ----
    #pragma unroll 4
    for (int i = 0; i < 16; ++i) {
        int o = t + 256 * i;
        int row = o >> 5, u = o & 31;
        cp_async16(a_base + row * A_ROWB + u * 16,
                   g_zh + (size_t)(q0 + row) * 256 + u * 8);
    }
    #pragma unroll
    for (int i = 0; i < 4; ++i) {
        int o = t + 256 * i;
        int row = o >> 3, u = o & 7;
        cp_async16(b_base + row * B_ROWB + u * 16,
                   g_cbh + (size_t)row * 256 + u * 8);
    }
    CP_COMMIT();

    float acc[2][8][4];
    #pragma unroll
    for (int m = 0; m < 2; ++m)
        #pragma unroll
        for (int j = 0; j < 8; ++j)
            #pragma unroll
            for (int r = 0; r < 4; ++r) acc[m][j][r] = 0.f;

    float bestv[4] = {3.4e38f, 3.4e38f, 3.4e38f, 3.4e38f};

    // ldmatrix lane addressing (conflict-free: row strides are odd 16B units)
    const int a_ro = (lane & 7) + ((lane >> 3) & 1) * 8;
    const int a_lc = lane >> 4;
    const int b_ro = (lane & 7) + ((lane >> 4) & 1) * 8;
    const int b_lc = (lane >> 3) & 1;
    const uint32_t a_ptr0 = a_base + (warp_m * 32 + a_ro) * A_ROWB + a_lc * 16;
    const uint32_t b_ptr0 = b_base + (warp_n * 64 + b_ro) * B_ROWB + b_lc * 16;

    // 32 chunks: ntile = gc/4 (code tile), kc = gc%4 (64-K slice)
    for (int gc = 0; gc < 32; ++gc) {
        const int s  = gc & 1;
        const int nt = gc >> 2;
        const int c  = gc & 3;

        if (gc + 1 < 32) {
            const int nt2 = (gc + 1) >> 2, kc2 = (gc + 1) & 3;
            const uint32_t dst = b_base + (uint32_t)(s ^ 1) * B_STAGE;
            #pragma unroll
            for (int i = 0; i < 4; ++i) {
                int o = t + 256 * i;
                int row = o >> 3, u = o & 7;
                cp_async16(dst + row * B_ROWB + u * 16,
                           g_cbh + (size_t)(nt2 * 128 + row) * 256 + kc2 * 64 + u * 8);
            }
            CP_COMMIT();
            CP_WAIT1();
        } else {
            CP_WAIT0();
        }
        __syncthreads();

        const uint32_t ap = a_ptr0 + (uint32_t)c * 128u;   // 64 bf16 = 128B per kc
        const uint32_t bp = b_ptr0 + (uint32_t)s * B_STAGE;

        #pragma unroll
        for (int j = 0; j < 4; ++j) {
            uint32_t a0[4], a1[4];
            ldsm4(a0, ap + j * 32);
            ldsm4(a1, ap + 16 * A_ROWB + j * 32);
            #pragma unroll
            for (int q = 0; q < 4; ++q) {
                uint32_t bq[4];
                ldsm4(bq, bp + q * (16 * B_ROWB) + j * 32);
                mma_bf16(acc[0][2 * q + 0], a0, bq + 0);
                mma_bf16(acc[0][2 * q + 1], a0, bq + 2);
                mma_bf16(acc[1][2 * q + 0], a1, bq + 0);
                mma_bf16(acc[1][2 * q + 1], a1, bq + 2);
            }
        }

        // end-of-code-tile epilogue: scores, running best, candidate collection
        if (c == 3) {
            #pragma unroll
            for (int m = 0; m < 2; ++m) {
                #pragma unroll
                for (int rh = 0; rh < 2; ++rh) {
                    const int sl = m * 2 + rh;
                    const float zn = zn_s[warp_m * 32 + m * 16 + rh * 8 + (lane >> 2)];
                    float sc16[16];
                    #pragma unroll
                    for (int jn = 0; jn < 8; ++jn) {
                        const int k0 = nt * 128 + warp_n * 64 + jn * 8 + (lane & 3) * 2;
                        float a0 = acc[m][jn][rh * 2 + 0];
                        float a1 = acc[m][jn][rh * 2 + 1];
                        sc16[2 * jn]     = __fadd_rn(__fadd_rn(zn, cn_s[k0]),
                                                     __fmul_rn(-2.f, a0));
                        sc16[2 * jn + 1] = __fadd_rn(__fadd_rn(zn, cn_s[k0 + 1]),
                                                     __fmul_rn(-2.f, a1));
                        acc[m][jn][rh * 2 + 0] = 0.f;
                        acc[m][jn][rh * 2 + 1] = 0.f;
                    }
                    #pragma unroll
                    for (int i = 0; i < 16; ++i)
                        if (sc16[i] < bestv[sl]) bestv[sl] = sc16[i];
                    // warp-quad running min -> collection threshold
                    float qm = bestv[sl];
                    qm = fminf(qm, __shfl_xor_sync(0xffffffffu, qm, 1));
                    qm = fminf(qm, __shfl_xor_sync(0xffffffffu, qm, 2));
                    const float thr = qm + EPS;
                    const int rowg = q0 + warp_m * 32 + m * 16 + rh * 8 + (lane >> 2);
                    #pragma unroll
                    for (int i = 0; i < 16; ++i) {
                        if (sc16[i] < thr) {
                            int k = nt * 128 + warp_n * 64 + (i >> 1) * 8
                                  + (lane & 3) * 2 + (i & 1);
                            int pos = atomicAdd(&g_cnt[rowg], 1);
                            if (pos < CAP) g_cand[rowg * CAP + pos] = k;
                        }
                    }
                }
            }
        }
        __syncthreads();   // all warps done with stage s before it is refilled
    }
}

// ---------------------------------------------------------------------------
// Exact fp32 re-rank of collected candidates (round-2 arithmetic, bit-matched)
// one warp per query; lex-min (value, index) = jnp.argmin semantics.
// ---------------------------------------------------------------------------
__global__ __launch_bounds__(256) void rerank_kernel(const float* __restrict__ cb) {
    const int warp = threadIdx.x >> 5, lane = threadIdx.x & 31;
    const int q = blockIdx.x * 8 + warp;   // 8 warps/block, NQ/8 blocks
    const int cnt = g_cnt[q];

    if (cnt == 1) {                       // unique candidate: already the winner
        if (lane == 0) g_idx[q] = g_cand[q * CAP];
        return;
    }

    const float zn = g_znorm[q];
    const float* zr = g_zt + (size_t)q * DD;
    float bv = 3.4e38f;
    int   bi = 0x7FFFFFFF;

    if (cnt <= CAP) {
        if (lane < cnt) {
            int k = g_cand[q * CAP + lane];
            const float* cr = cb + (size_t)k * DD;
            float acc = 0.f;
            for (int d = 0; d < DD; ++d) acc = fmaf(zr[d], cr[d], acc);
            bv = __fadd_rn(__fadd_rn(zn, g_cnorm[k]), __fmul_rn(-2.f, acc));
            bi = k;
        }
    } else {                              // overflow fallback: full exact scan
        for (int k = lane; k < KC; k += 32) {
            const float* cr = cb + (size_t)k * DD;
            float acc = 0.f;
            for (int d = 0; d < DD; ++d) acc = fmaf(zr[d], cr[d], acc);
            float sc = __fadd_rn(__fadd_rn(zn, g_cnorm[k]), __fmul_rn(-2.f, acc));
            if (sc < bv || (sc == bv && k < bi)) { bv = sc; bi = k; }
        }
    }
    #pragma unroll
    for (int off = 16; off >= 1; off >>= 1) {
        float v2 = __shfl_xor_sync(0xffffffffu, bv, off);
        int   i2 = __shfl_xor_sync(0xffffffffu, bi, off);
        if (v2 < bv || (v2 == bv && i2 < bi)) { bv = v2; bi = i2; }
    }
    if (lane == 0) g_idx[q] = bi;
}

// ---------------------------------------------------------------------------
// Gather z_q (NCHW via smem transpose) + loss partials
// ---------------------------------------------------------------------------
__global__ __launch_bounds__(256) void gather_kernel(
        const float* __restrict__ z, const float* __restrict__ cb,
        float* __restrict__ out_zq, float* __restrict__ out_idxf) {
    __shared__ float tile[32][129];
    __shared__ int   idx_s[128];
    __shared__ float red[256];

    const int t   = threadIdx.x;
    const int n0  = blockIdx.x * 128;
    const int b   = n0 >> 10;
    const int hw0 = n0 & 1023;

    if (t < 128) {
        int id = g_idx[n0 + t];
        idx_s[t] = id;
        out_idxf[n0 + t] = (float)id;
    }
    __syncthreads();

    float lsum = 0.f;
    for (int c0 = 0; c0 < DD; c0 += 32) {
        {
            int q = t >> 1, part = t & 1;
            const float* src = cb + (size_t)idx_s[q] * DD + c0 + part * 16;
            #pragma unroll
            for (int u = 0; u < 4; ++u) {
                float4 v = *reinterpret_cast<const float4*>(src + u * 4);
                int cc = part * 16 + u * 4;
                tile[cc + 0][q] = v.x; tile[cc + 1][q] = v.y;
                tile[cc + 2][q] = v.z; tile[cc + 3][q] = v.w;
            }
        }
        __syncthreads();
        #pragma unroll
        for (int i = 0; i < 16; ++i) {
            int lin = t + 256 * i;
            int cc  = lin >> 7;
            int q   = lin & 127;
            size_t gaddr = ((size_t)(b * 256 + c0 + cc)) * 1024 + hw0 + q;
            float v  = tile[cc][q];
            out_zq[gaddr] = v;
            float dv = v - z[gaddr];
            lsum = fmaf(dv, dv, lsum);
        }
        __syncthreads();
    }

    red[t] = lsum;
    __syncthreads();
    for (int s = 128; s > 0; s >>= 1) {
        if (t < s) red[t] += red[t + s];
        __syncthreads();
    }
    if (t == 0) g_part[blockIdx.x] = red[0];
}

__global__ void loss_kernel(float* __restrict__ out_loss) {
    __shared__ float red[256];
    int t = threadIdx.x;
    red[t] = g_part[t];
    __syncthreads();
    for (int s = 128; s > 0; s >>= 1) {
        if (t < s) red[t] += red[t + s];
        __syncthreads();
    }
    if (t == 0) out_loss[0] = 1.25f * red[0] / (float)ZQ_ELEMS;
}

// ---------------------------------------------------------------------------
extern "C" void kernel_launch(void* const* d_in, const int* in_sizes, int n_in,
                              void* d_out, int out_size) {
    const float* z  = (const float*)d_in[0];   // [32,256,32,32]
    const float* cb = (const float*)d_in[1];   // [1024,256]
    float* out      = (float*)d_out;
    float* out_zq   = out;
    float* out_loss = out + ZQ_ELEMS;
    float* out_idxf = out + ZQ_ELEMS + 1;

    cudaFuncSetAttribute(hmma_argmin_kernel,
                         cudaFuncAttributeMaxDynamicSharedMemorySize, DYN_SMEM);

    cnorm_kernel<<<4, 256>>>(cb);
    prep_cb_kernel<<<KC * DD / 256, 256>>>(cb);
    prep_z_kernel<<<dim3(32, 32, 8), dim3(32, 8)>>>(z);
    znorm_kernel<<<NQ / 128, 256>>>(z);
    hmma_argmin_kernel<<<NQ / 128, 256, DYN_SMEM>>>();
    rerank_kernel<<<NQ / 8, 256>>>(cb);
    gather_kernel<<<NQ / 128, 256>>>(z, cb, out_zq, out_idxf);
    loss_kernel<<<1, 256>>>(out_loss);
}